// round 1
// baseline (speedup 1.0000x reference)
#include <cuda_runtime.h>

// Problem constants
#define BB 2
#define SS 2048
#define DD 512
#define HH 8
#define HDIM 64
#define KROUTE 64
__device__ __constant__ float kScale = 0.125f; // 1/sqrt(64)

// Scratch (device globals; no allocation allowed)
__device__ float g_q[BB * HH * SS * HDIM];
__device__ float g_k[BB * HH * SS * HDIM];
__device__ float g_v[BB * HH * SS * HDIM];
__device__ float g_attn[BB * SS * DD];

// ---------------------------------------------------------------------------
// Generic 128x128x16 SIMT fp32 GEMM: C = A @ W + bias
//   A: [M, Kd] row-major, W: [Kd, N] row-major
//   MODE 0: C[m*N+n] = v      (final projection)
//   MODE 1: scatter into g_q/g_k/g_v with qkv head reshuffle (QKV epilogue)
// ---------------------------------------------------------------------------
template <int MODE>
__global__ __launch_bounds__(256) void gemm_k(
    const float* __restrict__ A, const float* __restrict__ W,
    const float* __restrict__ bias, float* __restrict__ C,
    int M, int N, int Kd)
{
    constexpr int BM = 128, BN = 128, BK = 16;
    __shared__ float As[BK][BM + 4];
    __shared__ float Bs[BK][BN];

    const int tid = threadIdx.x;
    const int tx = tid & 15;        // n-dim thread coord (16)
    const int ty = tid >> 4;        // m-dim thread coord (16)

    // A tile loader: 128 rows x 16 cols = 512 float4, 2 per thread
    const int aRow  = tid >> 2;          // 0..63 (+64 for second)
    const int aCol  = (tid & 3) << 2;    // 0,4,8,12
    // B tile loader: 16 rows x 128 cols = 512 float4, 2 per thread
    const int bRow  = tid >> 5;          // 0..7 (+8 for second)
    const int bCol  = (tid & 31) << 2;

    const float* Ap = A + (size_t)blockIdx.y * BM * Kd;
    const float* Wp = W + blockIdx.x * BN;

    float acc[8][8] = {};

    for (int k0 = 0; k0 < Kd; k0 += BK) {
        float4 a0 = *(const float4*)(Ap + (size_t)aRow * Kd + k0 + aCol);
        float4 a1 = *(const float4*)(Ap + (size_t)(aRow + 64) * Kd + k0 + aCol);
        float4 b0 = *(const float4*)(Wp + (size_t)(k0 + bRow) * N + bCol);
        float4 b1 = *(const float4*)(Wp + (size_t)(k0 + bRow + 8) * N + bCol);

        As[aCol + 0][aRow] = a0.x;
        As[aCol + 1][aRow] = a0.y;
        As[aCol + 2][aRow] = a0.z;
        As[aCol + 3][aRow] = a0.w;
        As[aCol + 0][aRow + 64] = a1.x;
        As[aCol + 1][aRow + 64] = a1.y;
        As[aCol + 2][aRow + 64] = a1.z;
        As[aCol + 3][aRow + 64] = a1.w;
        *(float4*)&Bs[bRow][bCol]     = b0;
        *(float4*)&Bs[bRow + 8][bCol] = b1;
        __syncthreads();

        #pragma unroll
        for (int kk = 0; kk < BK; kk++) {
            float ar[8], br[8];
            #pragma unroll
            for (int i = 0; i < 8; i++) ar[i] = As[kk][ty * 8 + i];
            #pragma unroll
            for (int j = 0; j < 8; j++) br[j] = Bs[kk][tx * 8 + j];
            #pragma unroll
            for (int i = 0; i < 8; i++)
                #pragma unroll
                for (int j = 0; j < 8; j++)
                    acc[i][j] = fmaf(ar[i], br[j], acc[i][j]);
        }
        __syncthreads();
    }

    #pragma unroll
    for (int i = 0; i < 8; i++) {
        const int m = blockIdx.y * BM + ty * 8 + i;
        #pragma unroll
        for (int j = 0; j < 8; j++) {
            const int n = blockIdx.x * BN + tx * 8 + j;
            const float v = acc[i][j] + bias[n];
            if (MODE == 0) {
                C[(size_t)m * N + n] = v;
            } else {
                // n = ((c3*H + h)*64 + d) within 1536; m = b*S + s
                const int b  = m >> 11;        // /2048
                const int s  = m & 2047;
                const int c3 = n >> 9;         // 0:q 1:k 2:v
                const int h  = (n >> 6) & 7;
                const int d  = n & 63;
                float* dst = (c3 == 0) ? g_q : (c3 == 1) ? g_k : g_v;
                dst[(((size_t)b * HH + h) * SS + s) * HDIM + d] = v;
            }
        }
    }
}

// ---------------------------------------------------------------------------
// Routed attention. One warp per query; each CTA owns 32 consecutive s for a
// single (b,h) so overlapping Cantor-route windows hit L1. Lane l holds dims
// 2l,2l+1 of q/out and owns scores kk=l and kk=l+32.
// ---------------------------------------------------------------------------
__global__ __launch_bounds__(256) void attn_k(const int* __restrict__ routes)
{
    const int lane = threadIdx.x & 31;
    const int warp = threadIdx.x >> 5;
    const int chunks = SS / 32;                   // 64
    const int bh = blockIdx.x / chunks;           // b*H + h
    const int sc = blockIdx.x % chunks;
    const int b = bh >> 3, h = bh & 7;

    const float* Qb = g_q + (size_t)bh * SS * HDIM;
    const float* Kb = g_k + (size_t)bh * SS * HDIM;
    const float* Vb = g_v + (size_t)bh * SS * HDIM;

    #pragma unroll 1
    for (int qi = 0; qi < 4; qi++) {
        const int s = sc * 32 + warp * 4 + qi;
        const float2 q = *(const float2*)(Qb + (size_t)s * HDIM + lane * 2);
        const int r_lo = routes[s * KROUTE + lane];
        const int r_hi = routes[s * KROUTE + 32 + lane];

        float sc_lo = 0.f, sc_hi = 0.f;
        #pragma unroll 8
        for (int kk = 0; kk < KROUTE; kk++) {
            const int r = __shfl_sync(0xffffffffu, (kk < 32) ? r_lo : r_hi, kk & 31);
            const float2 kv = *(const float2*)(Kb + (size_t)r * HDIM + lane * 2);
            float p = q.x * kv.x + q.y * kv.y;
            #pragma unroll
            for (int o = 16; o; o >>= 1) p += __shfl_xor_sync(0xffffffffu, p, o);
            if (lane == (kk & 31)) { if (kk < 32) sc_lo = p; else sc_hi = p; }
        }
        sc_lo *= kScale;
        sc_hi *= kScale;

        float mx = fmaxf(sc_lo, sc_hi);
        #pragma unroll
        for (int o = 16; o; o >>= 1) mx = fmaxf(mx, __shfl_xor_sync(0xffffffffu, mx, o));
        const float e_lo = __expf(sc_lo - mx);
        const float e_hi = __expf(sc_hi - mx);
        float sum = e_lo + e_hi;
        #pragma unroll
        for (int o = 16; o; o >>= 1) sum += __shfl_xor_sync(0xffffffffu, sum, o);
        const float inv = __fdividef(1.f, sum);
        const float w_lo = e_lo * inv, w_hi = e_hi * inv;

        float2 acc = make_float2(0.f, 0.f);
        #pragma unroll 8
        for (int kk = 0; kk < KROUTE; kk++) {
            const int r = __shfl_sync(0xffffffffu, (kk < 32) ? r_lo : r_hi, kk & 31);
            const float w = __shfl_sync(0xffffffffu, (kk < 32) ? w_lo : w_hi, kk & 31);
            const float2 vv = *(const float2*)(Vb + (size_t)r * HDIM + lane * 2);
            acc.x = fmaf(w, vv.x, acc.x);
            acc.y = fmaf(w, vv.y, acc.y);
        }
        // layout [b, s, h*64 + d] => directly the A matrix of the out-proj GEMM
        *(float2*)(g_attn + ((size_t)b * SS + s) * DD + h * HDIM + lane * 2) = acc;
    }
}

// ---------------------------------------------------------------------------
extern "C" void kernel_launch(void* const* d_in, const int* in_sizes, int n_in,
                              void* d_out, int out_size)
{
    const float* x     = (const float*)d_in[0];
    const float* Wqkv  = (const float*)d_in[1];
    const float* bqkv  = (const float*)d_in[2];
    const float* Wout  = (const float*)d_in[3];
    const float* bout  = (const float*)d_in[4];
    const int*   routes = (const int*)d_in[5];
    float* out = (float*)d_out;

    float* attnp = nullptr;
    cudaGetSymbolAddress((void**)&attnp, g_attn);

    // QKV: [4096,512] @ [512,1536] with head-scatter epilogue
    gemm_k<1><<<dim3(3 * DD / 128, (BB * SS) / 128), 256>>>(
        x, Wqkv, bqkv, nullptr, BB * SS, 3 * DD, DD);

    // Routed attention
    attn_k<<<BB * HH * (SS / 32), 256>>>(routes);

    // Out projection: [4096,512] @ [512,512]
    gemm_k<0><<<dim3(DD / 128, (BB * SS) / 128), 256>>>(
        attnp, Wout, bout, out, BB * SS, DD, DD);
}